// round 12
// baseline (speedup 1.0000x reference)
#include <cuda_runtime.h>

// ============================================================================
// RNN_29463475650831: GRU(T=11,F=3,H=11, reset_after) + Dense(121->7) + softmax
// B = 1,048,576. fp32. R10: f32x2 datapath with NO p2 arrays (named variables
// only) — 4 elems/thread as 2 packed lanes, weights (w,w)-duplicated in smem,
// each weight LDS serves both lanes (4 elems). 255-reg budget, 2 blocks/SM.
// ============================================================================

#define NTHREADS 128
#define B_TOTAL 1048576
#define PAIRS (B_TOTAL / 2)
#define LOG2E 1.4426950408889634f

typedef unsigned long long p2;   // packed f32x2

// Duplicated (w,w) weight image, p2 entries. Layout per j (48 entries):
//  0:bz 1:br 2:bh_in 3:bh_rec  4-6:Kz 7-9:Kr 10-12:Kh 13:pad
//  14-24:Rz 25-35:Rr 36-46:Rh 47:pad
// region D (528+): 8/(t,j): Wd[0..6],pad ; region Db (1496+): dense bias
#define WTOT 1504
__device__ __align__(16) float2 g_wdup[WTOT];

// Transposed input: pair planes [t*3+f][pair], entry=(x[2p],x[2p+1])
__device__ __align__(16) p2 g_xT[33u * PAIRS];   // 138 MB scratch

// ---------------- f32x2 / scalar helpers ----------------
static __device__ __forceinline__ p2 pk2(float lo, float hi) {
    p2 r; asm("mov.b64 %0, {%1, %2};" : "=l"(r) : "f"(lo), "f"(hi)); return r;
}
static __device__ __forceinline__ void up2(p2 a, float& lo, float& hi) {
    asm("mov.b64 {%0, %1}, %2;" : "=f"(lo), "=f"(hi) : "l"(a));
}
static __device__ __forceinline__ p2 ffma2(p2 a, p2 b, p2 c) {
    p2 d; asm("fma.rn.f32x2 %0, %1, %2, %3;" : "=l"(d) : "l"(a), "l"(b), "l"(c)); return d;
}
static __device__ __forceinline__ p2 fmul2(p2 a, p2 b) {
    p2 d; asm("mul.rn.f32x2 %0, %1, %2;" : "=l"(d) : "l"(a), "l"(b)); return d;
}
static __device__ __forceinline__ float fex2(float x) {
    float y; asm("ex2.approx.f32 %0, %1;" : "=f"(y) : "f"(x)); return y;
}
static __device__ __forceinline__ float frcp(float x) {
    float y; asm("rcp.approx.f32 %0, %1;" : "=f"(y) : "f"(x)); return y;
}
static __device__ __forceinline__ float tnh1(float x) {       // MUFU.TANH
    float y; asm("tanh.approx.f32 %0, %1;" : "=f"(y) : "f"(x)); return y;
}
// packed sigmoid: 0.5 + 0.5*tanh(0.5*x) per half
static __device__ __forceinline__ p2 sig2t(p2 a) {
    const p2 H = pk2(0.5f, 0.5f);
    p2 t = fmul2(a, H);
    float lo, hi; up2(t, lo, hi);
    return ffma2(pk2(tnh1(lo), tnh1(hi)), H, H);
}
// packed tanh
static __device__ __forceinline__ p2 tnh2t(p2 a) {
    float lo, hi; up2(a, lo, hi);
    return pk2(tnh1(lo), tnh1(hi));
}

// ---------------- weight image builder ----------------
static __device__ __forceinline__ float wval(int i,
                                             const float* K, const float* R,
                                             const float* bias, const float* Wd,
                                             const float* db) {
    float v = 0.0f;
    if (i < 528) {
        int j = i / 48, k = i % 48;
        if      (k == 0)  v = bias[j]      + bias[33 + j];
        else if (k == 1)  v = bias[11 + j] + bias[44 + j];
        else if (k == 2)  v = bias[22 + j];
        else if (k == 3)  v = bias[55 + j];
        else if (k < 7)   v = K[(k - 4)  * 33 + j];
        else if (k < 10)  v = K[(k - 7)  * 33 + 11 + j];
        else if (k < 13)  v = K[(k - 10) * 33 + 22 + j];
        else if (k == 13) v = 0.0f;
        else if (k < 25)  v = R[(k - 14) * 33 + j];
        else if (k < 36)  v = R[(k - 25) * 33 + 11 + j];
        else if (k < 47)  v = R[(k - 36) * 33 + 22 + j];
    } else if (i < 1496) {
        int d = i - 528, c = d & 7;
        if (c < 7) v = Wd[(d >> 3) * 7 + c];
    } else {
        int c = i - 1496;
        if (c < 7) v = db[c];
    }
    return v;
}

// ---------------- kernel 1: transpose x to pair planes + weight image -------
#define TP_ELEMS 256
__global__ __launch_bounds__(256)
void xpose_kernel(const float* __restrict__ x,
                  const float* __restrict__ K, const float* __restrict__ R,
                  const float* __restrict__ bias, const float* __restrict__ Wd,
                  const float* __restrict__ db) {
    __shared__ float tile[TP_ELEMS * 33];
    const unsigned base = blockIdx.x * (TP_ELEMS * 33u);
    #pragma unroll
    for (int k = 0; k < 33; k++) {
        int i = k * 256 + threadIdx.x;
        tile[i] = x[base + i];
    }
    if (blockIdx.x == 0) {
        for (int i = threadIdx.x; i < WTOT; i += 256) {
            float v = wval(i, K, R, bias, Wd, db);
            g_wdup[i] = make_float2(v, v);
        }
    }
    __syncthreads();
    float2* xt = reinterpret_cast<float2*>(g_xT);
    const unsigned pbase = blockIdx.x * (TP_ELEMS / 2);
    #pragma unroll 4
    for (int idx = threadIdx.x; idx < 33 * (TP_ELEMS / 2); idx += 256) {
        int plane = idx / (TP_ELEMS / 2);
        int pr    = idx % (TP_ELEMS / 2);
        float lo = tile[(2 * pr)     * 33 + plane];
        float hi = tile[(2 * pr + 1) * 33 + plane];
        xt[(size_t)plane * PAIRS + pbase + pr] = make_float2(lo, hi);
    }
}

// ---------------- per-(t,j) cell: both lanes, weights loaded once -----------
static __device__ __forceinline__ void cell2(
    const p2* __restrict__ W, const p2* __restrict__ wj,
    p2 x0A, p2 x1A, p2 x2A, p2 x0B, p2 x1B, p2 x2B,
    p2 h0A, p2 h1A, p2 h2A, p2 h3A, p2 h4A, p2 h5A, p2 h6A, p2 h7A, p2 h8A, p2 h9A, p2 h10A,
    p2 h0B, p2 h1B, p2 h2B, p2 h3B, p2 h4B, p2 h5B, p2 h6B, p2 h7B, p2 h8B, p2 h9B, p2 h10B,
    p2 hjA, p2 hjB, p2& hnA, p2& hnB,
    p2& c0A, p2& c1A, p2& c2A, p2& c3A, p2& c4A, p2& c5A, p2& c6A,
    p2& c0B, p2& c1B, p2& c2B, p2& c3B, p2& c4B, p2& c5B, p2& c6B)
{
    p2 w;
    w = W[0]; p2 azA = w, azB = w;
    w = W[1]; p2 arA = w, arB = w;
    w = W[2]; p2 ahA = w, ahB = w;
    w = W[3]; p2 bhA = w, bhB = w;
    w = W[4];  azA = ffma2(x0A, w, azA); azB = ffma2(x0B, w, azB);
    w = W[5];  azA = ffma2(x1A, w, azA); azB = ffma2(x1B, w, azB);
    w = W[6];  azA = ffma2(x2A, w, azA); azB = ffma2(x2B, w, azB);
    w = W[7];  arA = ffma2(x0A, w, arA); arB = ffma2(x0B, w, arB);
    w = W[8];  arA = ffma2(x1A, w, arA); arB = ffma2(x1B, w, arB);
    w = W[9];  arA = ffma2(x2A, w, arA); arB = ffma2(x2B, w, arB);
    w = W[10]; ahA = ffma2(x0A, w, ahA); ahB = ffma2(x0B, w, ahB);
    w = W[11]; ahA = ffma2(x1A, w, ahA); ahB = ffma2(x1B, w, ahB);
    w = W[12]; ahA = ffma2(x2A, w, ahA); ahB = ffma2(x2B, w, ahB);

    w = W[14]; azA = ffma2(h0A,  w, azA); azB = ffma2(h0B,  w, azB);
    w = W[15]; azA = ffma2(h1A,  w, azA); azB = ffma2(h1B,  w, azB);
    w = W[16]; azA = ffma2(h2A,  w, azA); azB = ffma2(h2B,  w, azB);
    w = W[17]; azA = ffma2(h3A,  w, azA); azB = ffma2(h3B,  w, azB);
    w = W[18]; azA = ffma2(h4A,  w, azA); azB = ffma2(h4B,  w, azB);
    w = W[19]; azA = ffma2(h5A,  w, azA); azB = ffma2(h5B,  w, azB);
    w = W[20]; azA = ffma2(h6A,  w, azA); azB = ffma2(h6B,  w, azB);
    w = W[21]; azA = ffma2(h7A,  w, azA); azB = ffma2(h7B,  w, azB);
    w = W[22]; azA = ffma2(h8A,  w, azA); azB = ffma2(h8B,  w, azB);
    w = W[23]; azA = ffma2(h9A,  w, azA); azB = ffma2(h9B,  w, azB);
    w = W[24]; azA = ffma2(h10A, w, azA); azB = ffma2(h10B, w, azB);

    w = W[25]; arA = ffma2(h0A,  w, arA); arB = ffma2(h0B,  w, arB);
    w = W[26]; arA = ffma2(h1A,  w, arA); arB = ffma2(h1B,  w, arB);
    w = W[27]; arA = ffma2(h2A,  w, arA); arB = ffma2(h2B,  w, arB);
    w = W[28]; arA = ffma2(h3A,  w, arA); arB = ffma2(h3B,  w, arB);
    w = W[29]; arA = ffma2(h4A,  w, arA); arB = ffma2(h4B,  w, arB);
    w = W[30]; arA = ffma2(h5A,  w, arA); arB = ffma2(h5B,  w, arB);
    w = W[31]; arA = ffma2(h6A,  w, arA); arB = ffma2(h6B,  w, arB);
    w = W[32]; arA = ffma2(h7A,  w, arA); arB = ffma2(h7B,  w, arB);
    w = W[33]; arA = ffma2(h8A,  w, arA); arB = ffma2(h8B,  w, arB);
    w = W[34]; arA = ffma2(h9A,  w, arA); arB = ffma2(h9B,  w, arB);
    w = W[35]; arA = ffma2(h10A, w, arA); arB = ffma2(h10B, w, arB);

    w = W[36]; bhA = ffma2(h0A,  w, bhA); bhB = ffma2(h0B,  w, bhB);
    w = W[37]; bhA = ffma2(h1A,  w, bhA); bhB = ffma2(h1B,  w, bhB);
    w = W[38]; bhA = ffma2(h2A,  w, bhA); bhB = ffma2(h2B,  w, bhB);
    w = W[39]; bhA = ffma2(h3A,  w, bhA); bhB = ffma2(h3B,  w, bhB);
    w = W[40]; bhA = ffma2(h4A,  w, bhA); bhB = ffma2(h4B,  w, bhB);
    w = W[41]; bhA = ffma2(h5A,  w, bhA); bhB = ffma2(h5B,  w, bhB);
    w = W[42]; bhA = ffma2(h6A,  w, bhA); bhB = ffma2(h6B,  w, bhB);
    w = W[43]; bhA = ffma2(h7A,  w, bhA); bhB = ffma2(h7B,  w, bhB);
    w = W[44]; bhA = ffma2(h8A,  w, bhA); bhB = ffma2(h8B,  w, bhB);
    w = W[45]; bhA = ffma2(h9A,  w, bhA); bhB = ffma2(h9B,  w, bhB);
    w = W[46]; bhA = ffma2(h10A, w, bhA); bhB = ffma2(h10B, w, bhB);

    const p2 N1 = pk2(-1.0f, -1.0f);
    p2 zA = sig2t(azA), zB = sig2t(azB);
    p2 rA = sig2t(arA), rB = sig2t(arB);
    p2 hhA = tnh2t(ffma2(rA, bhA, ahA));
    p2 hhB = tnh2t(ffma2(rB, bhB, ahB));
    p2 ddA = ffma2(hhA, N1, hjA);      // h - hh
    p2 ddB = ffma2(hhB, N1, hjB);
    hnA = ffma2(zA, ddA, hhA);
    hnB = ffma2(zB, ddB, hhB);

    w = wj[0]; c0A = ffma2(hnA, w, c0A); c0B = ffma2(hnB, w, c0B);
    w = wj[1]; c1A = ffma2(hnA, w, c1A); c1B = ffma2(hnB, w, c1B);
    w = wj[2]; c2A = ffma2(hnA, w, c2A); c2B = ffma2(hnB, w, c2B);
    w = wj[3]; c3A = ffma2(hnA, w, c3A); c3B = ffma2(hnB, w, c3B);
    w = wj[4]; c4A = ffma2(hnA, w, c4A); c4B = ffma2(hnB, w, c4B);
    w = wj[5]; c5A = ffma2(hnA, w, c5A); c5B = ffma2(hnB, w, c5B);
    w = wj[6]; c6A = ffma2(hnA, w, c6A); c6B = ffma2(hnB, w, c6B);
}

#define HL(L) h0##L,h1##L,h2##L,h3##L,h4##L,h5##L,h6##L,h7##L,h8##L,h9##L,h10##L
#define CL(L) c0##L,c1##L,c2##L,c3##L,c4##L,c5##L,c6##L
#define CELL(j) cell2(ws + (j)*48, wd + (j)*8, x0A,x1A,x2A, x0B,x1B,x2B, \
                      HL(A), HL(B), h##j##A, h##j##B, hn##j##A, hn##j##B, CL(A), CL(B))
#define CPH(i) h##i##A = hn##i##A; h##i##B = hn##i##B

// ---------------- kernel 2: main GRU (f32x2, named vars only) ---------------
__global__ __launch_bounds__(NTHREADS, 2)   // 255-reg budget
void gru_main(float* __restrict__ out) {
    __shared__ __align__(16) p2 ws[WTOT];
    {
        const float4* s = reinterpret_cast<const float4*>(g_wdup);
        float4* d = reinterpret_cast<float4*>(ws);
        #pragma unroll
        for (int i = threadIdx.x; i < WTOT / 2; i += NTHREADS) d[i] = s[i];
    }
    __syncthreads();

    const unsigned q  = blockIdx.x * NTHREADS + threadIdx.x;  // quad index
    const unsigned pb = 2u * q;                               // pair base (lanes A,B)

    p2 h0A=0,h1A=0,h2A=0,h3A=0,h4A=0,h5A=0,h6A=0,h7A=0,h8A=0,h9A=0,h10A=0;
    p2 h0B=0,h1B=0,h2B=0,h3B=0,h4B=0,h5B=0,h6B=0,h7B=0,h8B=0,h9B=0,h10B=0;
    p2 hn0A,hn1A,hn2A,hn3A,hn4A,hn5A,hn6A,hn7A,hn8A,hn9A,hn10A;
    p2 hn0B,hn1B,hn2B,hn3B,hn4B,hn5B,hn6B,hn7B,hn8B,hn9B,hn10B;

    p2 c0A,c1A,c2A,c3A,c4A,c5A,c6A, c0B,c1B,c2B,c3B,c4B,c5B,c6B;
    {
        p2 b;
        b = ws[1496]; c0A = b; c0B = b;
        b = ws[1497]; c1A = b; c1B = b;
        b = ws[1498]; c2A = b; c2B = b;
        b = ws[1499]; c3A = b; c3B = b;
        b = ws[1500]; c4A = b; c4B = b;
        b = ws[1501]; c5A = b; c5B = b;
        b = ws[1502]; c6A = b; c6B = b;
    }

    #pragma unroll 1
    for (int t = 0; t < 11; t++) {
        // 3 LDG.128: each loads both lanes' packed pair for one feature plane
        const ulonglong2 X0 = *reinterpret_cast<const ulonglong2*>(&g_xT[(size_t)(t * 3 + 0) * PAIRS + pb]);
        const ulonglong2 X1 = *reinterpret_cast<const ulonglong2*>(&g_xT[(size_t)(t * 3 + 1) * PAIRS + pb]);
        const ulonglong2 X2 = *reinterpret_cast<const ulonglong2*>(&g_xT[(size_t)(t * 3 + 2) * PAIRS + pb]);
        const p2 x0A = X0.x, x0B = X0.y;
        const p2 x1A = X1.x, x1B = X1.y;
        const p2 x2A = X2.x, x2B = X2.y;

        const p2* wd = ws + 528 + t * 88;

        CELL(0); CELL(1); CELL(2); CELL(3); CELL(4); CELL(5);
        CELL(6); CELL(7); CELL(8); CELL(9); CELL(10);

        CPH(0); CPH(1); CPH(2); CPH(3); CPH(4); CPH(5);
        CPH(6); CPH(7); CPH(8); CPH(9); CPH(10);
    }

    // softmax per element (4 elems: A.lo, A.hi, B.lo, B.hi) -> 7 STG.128
    float r28[28];
    {
        float lA[7], hA[7], lB[7], hB[7];
        up2(c0A, lA[0], hA[0]); up2(c1A, lA[1], hA[1]); up2(c2A, lA[2], hA[2]);
        up2(c3A, lA[3], hA[3]); up2(c4A, lA[4], hA[4]); up2(c5A, lA[5], hA[5]);
        up2(c6A, lA[6], hA[6]);
        up2(c0B, lB[0], hB[0]); up2(c1B, lB[1], hB[1]); up2(c2B, lB[2], hB[2]);
        up2(c3B, lB[3], hB[3]); up2(c4B, lB[4], hB[4]); up2(c5B, lB[5], hB[5]);
        up2(c6B, lB[6], hB[6]);
        const float* A4[4] = { lA, hA, lB, hB };
        #pragma unroll
        for (int v = 0; v < 4; v++) {
            const float* a = A4[v];
            float m = a[0];
            #pragma unroll
            for (int c = 1; c < 7; c++) m = fmaxf(m, a[c]);
            float ex[7], s = 0.0f;
            #pragma unroll
            for (int c = 0; c < 7; c++) { ex[c] = fex2((a[c] - m) * LOG2E); s += ex[c]; }
            float inv = frcp(s);
            #pragma unroll
            for (int c = 0; c < 7; c++) r28[v * 7 + c] = ex[c] * inv;
        }
    }
    float4* o4 = reinterpret_cast<float4*>(out + (size_t)q * 28);   // 112B, 16B-aligned
    #pragma unroll
    for (int k = 0; k < 7; k++)
        o4[k] = make_float4(r28[4 * k], r28[4 * k + 1], r28[4 * k + 2], r28[4 * k + 3]);
}

// ---------------- launch ----------------
extern "C" void kernel_launch(void* const* d_in, const int* in_sizes, int n_in,
                              void* d_out, int out_size) {
    const float* x    = (const float*)d_in[0];   // [B, 11, 3]
    const float* K    = (const float*)d_in[1];   // [3, 33]
    const float* R    = (const float*)d_in[2];   // [11, 33]
    const float* bias = (const float*)d_in[3];   // [2, 33]
    const float* Wd   = (const float*)d_in[4];   // [121, 7]
    const float* db   = (const float*)d_in[5];   // [7]
    float* out = (float*)d_out;                  // [B, 7]

    xpose_kernel<<<B_TOTAL / TP_ELEMS, 256>>>(x, K, R, bias, Wd, db);
    gru_main<<<(B_TOTAL / 4) / NTHREADS, NTHREADS>>>(out);
}